// round 12
// baseline (speedup 1.0000x reference)
#include <cuda_runtime.h>
#include <cuda_fp16.h>
#include <cstdint>

// Problem dims
constexpr int Lt = 128;
constexpr int Bt = 128;
constexpr int Hd = 1024;
constexpr int Gd = 4 * Hd;       // 4096
constexpr int KA = 512;          // K of both phase-1 sub-GEMMs

// Static scratch
__device__ float g_gx_act[(size_t)Lt * Bt * Gd];     // act-side gate projections
__device__ float g_gx_inp[(size_t)Bt * Gd];          // input-side + biases
__device__ __align__(16) __half g_act_h[(size_t)Lt * Bt * KA];
__device__ __align__(16) __half g_inp_h[(size_t)Bt * KA];
__device__ __align__(16) __half g_wih_h[(size_t)Gd * 1024];
__device__ __align__(16) __half g_hbuf_h[2][Bt * Hd];
__device__ unsigned g_bar_count;
__device__ unsigned g_bar_gen;

// ---------------------------------------------------------------- helpers
__device__ __forceinline__ uint32_t h2u(__half2 v) {
    __half2_raw r = *(__half2_raw*)&v;
    return (uint32_t)r.x | ((uint32_t)r.y << 16);
}
__device__ __forceinline__ void mma16(float* c, const uint32_t* a,
                                      uint32_t b0, uint32_t b1) {
    asm volatile(
        "mma.sync.aligned.m16n8k16.row.col.f32.f16.f16.f32 "
        "{%0,%1,%2,%3},{%4,%5,%6,%7},{%8,%9},{%0,%1,%2,%3};"
        : "+f"(c[0]), "+f"(c[1]), "+f"(c[2]), "+f"(c[3])
        : "r"(a[0]), "r"(a[1]), "r"(a[2]), "r"(a[3]), "r"(b0), "r"(b1));
}
__device__ __forceinline__ void ldsm4(uint32_t& d0, uint32_t& d1,
                                      uint32_t& d2, uint32_t& d3, uint32_t a) {
    asm volatile("ldmatrix.sync.aligned.m8n8.x4.shared.b16 {%0,%1,%2,%3}, [%4];"
                 : "=r"(d0), "=r"(d1), "=r"(d2), "=r"(d3) : "r"(a));
}
__device__ __forceinline__ void cpa16(uint32_t d, const void* s) {
    asm volatile("cp.async.cg.shared.global [%0], [%1], 16;" :: "r"(d), "l"(s));
}
__device__ __forceinline__ void cpcommit() { asm volatile("cp.async.commit_group;"); }
template<int N> __device__ __forceinline__ void cpwait() {
    asm volatile("cp.async.wait_group %0;" :: "n"(N));
}
__device__ __forceinline__ uint32_t s2u(const void* p) {
    return (uint32_t)__cvta_generic_to_shared(p);
}
__device__ __forceinline__ float sigm(float x) { return 1.0f / (1.0f + expf(-x)); }
__device__ __forceinline__ unsigned ldacq(const unsigned* p) {
    unsigned v;
    asm volatile("ld.acquire.gpu.global.u32 %0, [%1];" : "=r"(v) : "l"(p) : "memory");
    return v;
}
__device__ __forceinline__ void redrel(unsigned* p, unsigned v) {
    asm volatile("red.release.gpu.global.add.u32 [%0], %1;" :: "l"(p), "r"(v) : "memory");
}

// ============================================================================
// Prep: fp16-convert act / inp / W_ih; reset sync counters.
// ============================================================================
__global__ void prep_kernel(const float* __restrict__ act,
                            const float* __restrict__ inp,
                            const float* __restrict__ Wih) {
    if (blockIdx.x == 0 && threadIdx.x == 0) { g_bar_count = 0; g_bar_gen = 0; }
    const size_t NW = (size_t)Gd * 1024 / 8;      // 8-elem groups
    const size_t NA = (size_t)Lt * Bt * KA / 8;
    const size_t NI = (size_t)Bt * KA / 8;
    const size_t total = NW + NA + NI;
    for (size_t i = (size_t)blockIdx.x * blockDim.x + threadIdx.x; i < total;
         i += (size_t)gridDim.x * blockDim.x) {
        const float4* s; uint4* d;
        if (i < NW)           { s = (const float4*)Wih + 2 * i;            d = (uint4*)g_wih_h + i; }
        else if (i < NW + NA) { s = (const float4*)act + 2 * (i - NW);     d = (uint4*)g_act_h + (i - NW); }
        else                  { s = (const float4*)inp + 2 * (i - NW - NA); d = (uint4*)g_inp_h + (i - NW - NA); }
        float4 v0 = s[0], v1 = s[1];
        uint4 o;
        o.x = h2u(__floats2half2_rn(v0.x, v0.y));
        o.y = h2u(__floats2half2_rn(v0.z, v0.w));
        o.z = h2u(__floats2half2_rn(v1.x, v1.y));
        o.w = h2u(__floats2half2_rn(v1.z, v1.w));
        *d = o;
    }
}

// ============================================================================
// Phase 1: fp16 m16n8k16 GEMM (R10 coalesced staging). Input-tile epilogue
// folds (b_ih + b_hh) into g_gx_inp (deterministic across graph replays).
// ============================================================================
constexpr int P1_STG = 4;
constexpr int P1_STAGE_B = 2 * 128 * 32 * 2;   // A 8KB + B 8KB = 16 KB
constexpr int P1_SMEM = P1_STG * P1_STAGE_B;   // 64 KB

__global__ void __launch_bounds__(256, 2) gemm_x_h(const float* __restrict__ bih,
                                                   const float* __restrict__ bhh) {
    extern __shared__ char sm1[];
    const uint32_t sBase = s2u(sm1);

    const int tid = threadIdx.x, lane = tid & 31, warp = tid >> 5;
    const int wm = warp & 3, wn = warp >> 2;
    const bool isInp = (blockIdx.y == 128);
    const int bm = isInp ? 0 : blockIdx.y * 128;
    const int bn = blockIdx.x * 128;
    const __half* Ab = isInp ? g_inp_h : g_act_h + (size_t)bm * KA;
    const __half* Bb = g_wih_h + (size_t)bn * 1024 + (isInp ? 0 : 512);
    float* Cb = isInp ? g_gx_inp : g_gx_act + (size_t)bm * Gd;

    const int c4 = lane & 3;
    const int r8 = lane >> 2;

    auto loadblk = [&](int kb) {
        if (kb < 16) {
            uint32_t st = sBase + (uint32_t)(kb & 3) * P1_STAGE_B;
            #pragma unroll
            for (int j = 0; j < 2; j++) {
                int r = (warp * 2 + j) * 8 + r8;
                uint32_t off = (uint32_t)(((r >> 3) * 4 + c4) * 128
                             + (((r & 7) ^ c4) * 16));
                cpa16(st + off, Ab + (size_t)r * KA + kb * 32 + c4 * 8);
                cpa16(st + 8192 + off, Bb + (size_t)r * 1024 + kb * 32 + c4 * 8);
            }
        }
        cpcommit();
    };

    loadblk(0); loadblk(1); loadblk(2);

    float acc[2][8][4];
    #pragma unroll
    for (int i = 0; i < 2; i++)
        #pragma unroll
        for (int j = 0; j < 8; j++)
            #pragma unroll
            for (int k = 0; k < 4; k++) acc[i][j][k] = 0.0f;

    const int g = lane >> 3;
    const int l7 = lane & 7;

    for (int kb = 0; kb < 16; kb++) {
        cpwait<2>(); __syncthreads();
        loadblk(kb + 3);
        const uint32_t stA = sBase + (uint32_t)(kb & 3) * P1_STAGE_B;
        const uint32_t stB = stA + 8192;

        #pragma unroll
        for (int kc = 0; kc < 2; kc++) {
            uint32_t a[2][4];
            #pragma unroll
            for (int tm = 0; tm < 2; tm++) {
                int rt = wm * 4 + tm * 2 + (g & 1);
                int ct = kc * 2 + (g >> 1);
                ldsm4(a[tm][0], a[tm][1], a[tm][2], a[tm][3],
                      stA + (uint32_t)((rt * 4 + ct) * 128 + ((l7 ^ ct) * 16)));
            }
            #pragma unroll
            for (int j = 0; j < 4; j++) {
                int nt = wn * 8 + 2 * j + (g >> 1);
                int ct = kc * 2 + (g & 1);
                uint32_t b0, b1, b2, b3;
                ldsm4(b0, b1, b2, b3,
                      stB + (uint32_t)((nt * 4 + ct) * 128 + ((l7 ^ ct) * 16)));
                mma16(acc[0][2 * j],     a[0], b0, b1);
                mma16(acc[0][2 * j + 1], a[0], b2, b3);
                mma16(acc[1][2 * j],     a[1], b0, b1);
                mma16(acc[1][2 * j + 1], a[1], b2, b3);
            }
        }
    }

    #pragma unroll
    for (int tm = 0; tm < 2; tm++) {
        int rr = wm * 32 + tm * 16 + (lane >> 2);
        #pragma unroll
        for (int tn = 0; tn < 8; tn++) {
            int cc = bn + wn * 64 + tn * 8 + 2 * (lane & 3);
            float bv0 = 0.0f, bv1 = 0.0f;
            if (isInp) {
                bv0 = bih[cc] + bhh[cc];
                bv1 = bih[cc + 1] + bhh[cc + 1];
            }
            *(float2*)&Cb[(size_t)rr * Gd + cc] =
                make_float2(acc[tm][tn][0] + bv0, acc[tm][tn][1] + bv1);
            *(float2*)&Cb[(size_t)(rr + 8) * Gd + cc] =
                make_float2(acc[tm][tn][2] + bv0, acc[tm][tn][3] + bv1);
        }
    }
}

// ============================================================================
// Phase 2: persistent LSTM recurrence. 64 CTAs x 16 hidden units each.
// W slice 128 KB fp16 smem (8 tiles x 128 chunks x 128 B); 3 x 32KB h slots;
// coalesced staging; per-CTA stagger; 64-participant barrier.
// ============================================================================
constexpr int NTHR = 256;
constexpr int NCTA2 = 64;
constexpr int WS_B = 8 * 128 * 128;             // 128 KB W tiles (FIXED)
constexpr int SLOT2_B = 128 * 128 * 2;          // 32 KB per 128-col slot
constexpr int SMEM2 = WS_B + 3 * SLOT2_B;       // 229376 B = 224 KB

__device__ __forceinline__ void gbar(unsigned target) {
    __syncthreads();
    if (threadIdx.x == 0) {
        __threadfence();
        unsigned old = atomicAdd(&g_bar_count, 1u);
        if ((old + 1u) % gridDim.x == 0u) {
            __threadfence();
            redrel(&g_bar_gen, 1u);
        } else {
            while (ldacq(&g_bar_gen) < target) { }
        }
        __threadfence();
    }
    __syncthreads();
}

__global__ void __launch_bounds__(NTHR, 1) lstm_seq_kernel(
    const float* __restrict__ h0, const float* __restrict__ c0in,
    const float* __restrict__ Whh, float* __restrict__ out, int out_size)
{
    extern __shared__ char sm2[];
    const uint32_t sW = s2u(sm2);
    const uint32_t sSt = sW + WS_B;

    const int tid = threadIdx.x, lane = tid & 31, warp = tid >> 5;
    const int cta = blockIdx.x;
    const int ub  = cta * 16;
    const int ul  = 2 * (lane & 3);
    const int b0  = warp * 16 + (lane >> 2);
    const int stag = cta & 7;

    // --- W_hh slice (16 units) -> smem fp16 as (gate, oct, chunk) tiles
    for (int i = tid; i < 64 * 128; i += NTHR) {
        int lr = i >> 7;                    // 0..63
        int c  = i & 127;                   // k-chunk (8 halves)
        int gate = lr >> 4, unit = lr & 15;
        const float* src = Whh + (size_t)(gate * Hd + ub + unit) * Hd + c * 8;
        float4 v0 = *(const float4*)src;
        float4 v1 = *(const float4*)(src + 4);
        uint4 o;
        o.x = h2u(__floats2half2_rn(v0.x, v0.y));
        o.y = h2u(__floats2half2_rn(v0.z, v0.w));
        o.z = h2u(__floats2half2_rn(v1.x, v1.y));
        o.w = h2u(__floats2half2_rn(v1.z, v1.w));
        int tile = gate * 2 + (unit >> 3);
        uint32_t off = (uint32_t)((tile * 128 + c) * 128
                     + (((unit & 7) ^ (c & 7)) * 16));
        *(uint4*)(sm2 + off) = o;
    }

    // c state: creg[oct][bs][us]
    float creg[2][2][2];
    #pragma unroll
    for (int o = 0; o < 2; o++)
        #pragma unroll
        for (int bs = 0; bs < 2; bs++) {
            int b = b0 + bs * 8;
            int u = ub + 8 * o + ul;
            creg[o][bs][0] = c0in[(size_t)b * Hd + u];
            creg[o][bs][1] = c0in[(size_t)b * Hd + u + 1];
        }

    // initial h (fp16) -> buffer 0: this CTA covers batch rows 2cta, 2cta+1
    #pragma unroll
    for (int rr = 0; rr < 2; rr++) {
        int row = 2 * cta + rr;
        for (int i = tid; i < Hd / 2; i += NTHR) {
            float2 v = *(const float2*)&h0[(size_t)row * Hd + 2 * i];
            *(__half2*)&g_hbuf_h[0][row * Hd + 2 * i] = __floats2half2_rn(v.x, v.y);
        }
    }
    gbar(1);

    // coalesced staging geometry (R10): warp reads 2 x 256B contiguous rows
    const int srow_half = lane >> 4;
    const int sc = lane & 15;
    const int shalf = sc >> 3, scc = sc & 7;
    const int g = lane >> 3, l7 = lane & 7;

    for (int t = 0; t < Lt; t++) {
        const __half* cur = g_hbuf_h[t & 1];
        __half* nxt = g_hbuf_h[(t + 1) & 1];

        // combined x-side gates: gx[q][oct][bs] (gxa from DRAM + gxi incl bias)
        float2 gx[4][2][2];
        #pragma unroll
        for (int q = 0; q < 4; q++)
            #pragma unroll
            for (int o = 0; o < 2; o++)
                #pragma unroll
                for (int bs = 0; bs < 2; bs++) {
                    int b = b0 + bs * 8;
                    int u = ub + 8 * o + ul;
                    float2 va = *(const float2*)
                        &g_gx_act[((size_t)t * Bt + b) * Gd + q * Hd + u];
                    float2 vi = *(const float2*)
                        &g_gx_inp[(size_t)b * Gd + q * Hd + u];
                    gx[q][o][bs] = make_float2(va.x + vi.x, va.y + vi.y);
                }

        float acc[4][2][4];
        #pragma unroll
        for (int q = 0; q < 4; q++)
            #pragma unroll
            for (int o = 0; o < 2; o++)
                #pragma unroll
                for (int k = 0; k < 4; k++) acc[q][o][k] = 0.0f;

        // stage slot j%3 with k-slot (j+stag)&7 (128 cols)
        auto stage = [&](int j) {
            if (j < 8) {
                int ks = (j + stag) & 7;
                uint32_t st = sSt + (uint32_t)(j % 3) * SLOT2_B;
                #pragma unroll
                for (int jj = 0; jj < 8; jj++) {
                    int r = (warp * 8 + jj) * 2 + srow_half;
                    uint32_t off = (uint32_t)(shalf * 16384
                                 + ((r >> 3) * 8 + scc) * 128
                                 + (((r & 7) ^ scc) * 16));
                    cpa16(st + off, cur + (size_t)r * Hd + ks * 128 + sc * 8);
                }
            }
            cpcommit();
        };

        stage(0); stage(1);

        for (int i = 0; i < 8; i++) {
            cpwait<1>(); __syncthreads();
            stage(i + 2);
            const int ks = (i + stag) & 7;
            #pragma unroll
            for (int h = 0; h < 2; h++) {
                const uint32_t st = sSt + (uint32_t)(i % 3) * SLOT2_B
                                  + (uint32_t)h * 16384;
                const int kbg = 2 * ks + h;

                #pragma unroll
                for (int kc = 0; kc < 4; kc++) {
                    uint32_t a[4];
                    {
                        int rt = warp * 2 + (g & 1);
                        int ct = kc * 2 + (g >> 1);
                        ldsm4(a[0], a[1], a[2], a[3],
                              st + (uint32_t)((rt * 8 + ct) * 128 + ((l7 ^ ct) * 16)));
                    }
                    #pragma unroll
                    for (int p = 0; p < 2; p++)
                        #pragma unroll
                        for (int o = 0; o < 2; o++) {
                            int gate = 2 * p + (g >> 1);
                            int tile = gate * 2 + o;
                            int ctg = kbg * 8 + kc * 2 + (g & 1);
                            uint32_t b0r, b1r, b2r, b3r;
                            ldsm4(b0r, b1r, b2r, b3r,
                                  sW + (uint32_t)((tile * 128 + ctg) * 128
                                       + ((l7 ^ (ctg & 7)) * 16)));
                            mma16(acc[2 * p][o],     a, b0r, b1r);
                            mma16(acc[2 * p + 1][o], a, b2r, b3r);
                        }
                }
            }
        }

        // cell update per oct
        #pragma unroll
        for (int o = 0; o < 2; o++)
            #pragma unroll
            for (int bs = 0; bs < 2; bs++) {
                int b = b0 + bs * 8;
                int u = ub + 8 * o + ul;
                float hv[2], cv[2];
                #pragma unroll
                for (int us = 0; us < 2; us++) {
                    int ci = bs * 2 + us;
                    float gi = acc[0][o][ci] + (us ? gx[0][o][bs].y : gx[0][o][bs].x);
                    float gf = acc[1][o][ci] + (us ? gx[1][o][bs].y : gx[1][o][bs].x);
                    float gg = acc[2][o][ci] + (us ? gx[2][o][bs].y : gx[2][o][bs].x);
                    float go = acc[3][o][ci] + (us ? gx[3][o][bs].y : gx[3][o][bs].x);
                    float cn = sigm(gf) * creg[o][bs][us] + sigm(gi) * tanhf(gg);
                    float hn = sigm(go) * tanhf(cn);
                    creg[o][bs][us] = cn;
                    hv[us] = hn; cv[us] = cn;
                }
                size_t ob = (size_t)t * Bt * Hd + (size_t)b * Hd + u;
                *(float2*)&out[ob] = make_float2(hv[0], hv[1]);
                if (t + 1 < Lt) {
                    *(__half2*)&nxt[b * Hd + u] = __floats2half2_rn(hv[0], hv[1]);
                } else {
                    size_t HS = (size_t)Lt * Bt * Hd;
                    if ((size_t)out_size >= HS + 2 * (size_t)Bt * Hd) {
                        *(float2*)&out[HS + (size_t)b * Hd + u] =
                            make_float2(hv[0], hv[1]);
                        *(float2*)&out[HS + (size_t)Bt * Hd + (size_t)b * Hd + u] =
                            make_float2(cv[0], cv[1]);
                    }
                }
            }
        if (t + 1 < Lt) gbar((unsigned)(t + 2));
    }
}

extern "C" void kernel_launch(void* const* d_in, const int* in_sizes, int n_in,
                              void* d_out, int out_size) {
    (void)in_sizes; (void)n_in;
    const float* act = (const float*)d_in[0];
    const float* inp = (const float*)d_in[1];
    const float* h0  = (const float*)d_in[2];
    const float* c0  = (const float*)d_in[3];
    const float* Wih = (const float*)d_in[4];
    const float* Whh = (const float*)d_in[5];
    const float* bih = (const float*)d_in[6];
    const float* bhh = (const float*)d_in[7];
    float* out = (float*)d_out;

    cudaFuncSetAttribute(gemm_x_h,
                         cudaFuncAttributeMaxDynamicSharedMemorySize, P1_SMEM);
    cudaFuncSetAttribute(lstm_seq_kernel,
                         cudaFuncAttributeMaxDynamicSharedMemorySize, SMEM2);

    prep_kernel<<<1024, 256>>>(act, inp, Wih);
    gemm_x_h<<<dim3(32, 129), 256, P1_SMEM>>>(bih, bhh);
    lstm_seq_kernel<<<NCTA2, NTHR, SMEM2>>>(h0, c0, Whh, out, out_size);
}

// round 13
// speedup vs baseline: 1.1705x; 1.1705x over previous
#include <cuda_runtime.h>
#include <cuda_fp16.h>
#include <cstdint>

// Problem dims
constexpr int Lt = 128;
constexpr int Bt = 128;
constexpr int Hd = 1024;
constexpr int Gd = 4 * Hd;       // 4096
constexpr int KA = 512;          // K of both phase-1 sub-GEMMs

// Static scratch
__device__ float g_gx_act[(size_t)Lt * Bt * Gd];     // act-side gate projections
__device__ float g_gx_inp[(size_t)Bt * Gd];          // input-side + biases
__device__ __align__(16) __half g_act_h[(size_t)Lt * Bt * KA];
__device__ __align__(16) __half g_inp_h[(size_t)Bt * KA];
__device__ __align__(16) __half g_wih_h[(size_t)Gd * 1024];
__device__ __align__(16) __half g_hring[4][Bt * Hd]; // 4-deep h ring
__device__ unsigned g_chunk_cnt[8];                  // producer counters (128-col chunks)
__device__ unsigned g_read_done[4];                  // per-slot WAR counters
__device__ unsigned g_bar_count;
__device__ unsigned g_bar_gen;

// ---------------------------------------------------------------- helpers
__device__ __forceinline__ uint32_t h2u(__half2 v) {
    __half2_raw r = *(__half2_raw*)&v;
    return (uint32_t)r.x | ((uint32_t)r.y << 16);
}
__device__ __forceinline__ void mma16(float* c, const uint32_t* a,
                                      uint32_t b0, uint32_t b1) {
    asm volatile(
        "mma.sync.aligned.m16n8k16.row.col.f32.f16.f16.f32 "
        "{%0,%1,%2,%3},{%4,%5,%6,%7},{%8,%9},{%0,%1,%2,%3};"
        : "+f"(c[0]), "+f"(c[1]), "+f"(c[2]), "+f"(c[3])
        : "r"(a[0]), "r"(a[1]), "r"(a[2]), "r"(a[3]), "r"(b0), "r"(b1));
}
__device__ __forceinline__ void ldsm4(uint32_t& d0, uint32_t& d1,
                                      uint32_t& d2, uint32_t& d3, uint32_t a) {
    asm volatile("ldmatrix.sync.aligned.m8n8.x4.shared.b16 {%0,%1,%2,%3}, [%4];"
                 : "=r"(d0), "=r"(d1), "=r"(d2), "=r"(d3) : "r"(a));
}
__device__ __forceinline__ void cpa16(uint32_t d, const void* s) {
    asm volatile("cp.async.cg.shared.global [%0], [%1], 16;" :: "r"(d), "l"(s));
}
__device__ __forceinline__ void cpcommit() { asm volatile("cp.async.commit_group;"); }
template<int N> __device__ __forceinline__ void cpwait() {
    asm volatile("cp.async.wait_group %0;" :: "n"(N));
}
__device__ __forceinline__ uint32_t s2u(const void* p) {
    return (uint32_t)__cvta_generic_to_shared(p);
}
__device__ __forceinline__ float sigm(float x) { return 1.0f / (1.0f + expf(-x)); }
__device__ __forceinline__ unsigned ldacq(const unsigned* p) {
    unsigned v;
    asm volatile("ld.acquire.gpu.global.u32 %0, [%1];" : "=r"(v) : "l"(p) : "memory");
    return v;
}
__device__ __forceinline__ void redrel(unsigned* p, unsigned v) {
    asm volatile("red.release.gpu.global.add.u32 [%0], %1;" :: "l"(p), "r"(v) : "memory");
}

// ============================================================================
// Prep: fp16-convert act / inp / W_ih; reset all sync counters.
// ============================================================================
__global__ void prep_kernel(const float* __restrict__ act,
                            const float* __restrict__ inp,
                            const float* __restrict__ Wih) {
    if (blockIdx.x == 0 && threadIdx.x == 0) {
        g_bar_count = 0; g_bar_gen = 0;
        #pragma unroll
        for (int i = 0; i < 8; i++) g_chunk_cnt[i] = 0;
        #pragma unroll
        for (int i = 0; i < 4; i++) g_read_done[i] = 0;
    }
    const size_t NW = (size_t)Gd * 1024 / 8;      // 8-elem groups
    const size_t NA = (size_t)Lt * Bt * KA / 8;
    const size_t NI = (size_t)Bt * KA / 8;
    const size_t total = NW + NA + NI;
    for (size_t i = (size_t)blockIdx.x * blockDim.x + threadIdx.x; i < total;
         i += (size_t)gridDim.x * blockDim.x) {
        const float4* s; uint4* d;
        if (i < NW)           { s = (const float4*)Wih + 2 * i;            d = (uint4*)g_wih_h + i; }
        else if (i < NW + NA) { s = (const float4*)act + 2 * (i - NW);     d = (uint4*)g_act_h + (i - NW); }
        else                  { s = (const float4*)inp + 2 * (i - NW - NA); d = (uint4*)g_inp_h + (i - NW - NA); }
        float4 v0 = s[0], v1 = s[1];
        uint4 o;
        o.x = h2u(__floats2half2_rn(v0.x, v0.y));
        o.y = h2u(__floats2half2_rn(v0.z, v0.w));
        o.z = h2u(__floats2half2_rn(v1.x, v1.y));
        o.w = h2u(__floats2half2_rn(v1.z, v1.w));
        *d = o;
    }
}

// ============================================================================
// Phase 1: fp16 m16n8k16 GEMM (R10 coalesced staging + R12 bias fold).
// ============================================================================
constexpr int P1_STG = 4;
constexpr int P1_STAGE_B = 2 * 128 * 32 * 2;   // A 8KB + B 8KB = 16 KB
constexpr int P1_SMEM = P1_STG * P1_STAGE_B;   // 64 KB

__global__ void __launch_bounds__(256, 2) gemm_x_h(const float* __restrict__ bih,
                                                   const float* __restrict__ bhh) {
    extern __shared__ char sm1[];
    const uint32_t sBase = s2u(sm1);

    const int tid = threadIdx.x, lane = tid & 31, warp = tid >> 5;
    const int wm = warp & 3, wn = warp >> 2;
    const bool isInp = (blockIdx.y == 128);
    const int bm = isInp ? 0 : blockIdx.y * 128;
    const int bn = blockIdx.x * 128;
    const __half* Ab = isInp ? g_inp_h : g_act_h + (size_t)bm * KA;
    const __half* Bb = g_wih_h + (size_t)bn * 1024 + (isInp ? 0 : 512);
    float* Cb = isInp ? g_gx_inp : g_gx_act + (size_t)bm * Gd;

    const int c4 = lane & 3;
    const int r8 = lane >> 2;

    auto loadblk = [&](int kb) {
        if (kb < 16) {
            uint32_t st = sBase + (uint32_t)(kb & 3) * P1_STAGE_B;
            #pragma unroll
            for (int j = 0; j < 2; j++) {
                int r = (warp * 2 + j) * 8 + r8;
                uint32_t off = (uint32_t)(((r >> 3) * 4 + c4) * 128
                             + (((r & 7) ^ c4) * 16));
                cpa16(st + off, Ab + (size_t)r * KA + kb * 32 + c4 * 8);
                cpa16(st + 8192 + off, Bb + (size_t)r * 1024 + kb * 32 + c4 * 8);
            }
        }
        cpcommit();
    };

    loadblk(0); loadblk(1); loadblk(2);

    float acc[2][8][4];
    #pragma unroll
    for (int i = 0; i < 2; i++)
        #pragma unroll
        for (int j = 0; j < 8; j++)
            #pragma unroll
            for (int k = 0; k < 4; k++) acc[i][j][k] = 0.0f;

    const int g = lane >> 3;
    const int l7 = lane & 7;

    for (int kb = 0; kb < 16; kb++) {
        cpwait<2>(); __syncthreads();
        loadblk(kb + 3);
        const uint32_t stA = sBase + (uint32_t)(kb & 3) * P1_STAGE_B;
        const uint32_t stB = stA + 8192;

        #pragma unroll
        for (int kc = 0; kc < 2; kc++) {
            uint32_t a[2][4];
            #pragma unroll
            for (int tm = 0; tm < 2; tm++) {
                int rt = wm * 4 + tm * 2 + (g & 1);
                int ct = kc * 2 + (g >> 1);
                ldsm4(a[tm][0], a[tm][1], a[tm][2], a[tm][3],
                      stA + (uint32_t)((rt * 4 + ct) * 128 + ((l7 ^ ct) * 16)));
            }
            #pragma unroll
            for (int j = 0; j < 4; j++) {
                int nt = wn * 8 + 2 * j + (g >> 1);
                int ct = kc * 2 + (g & 1);
                uint32_t b0, b1, b2, b3;
                ldsm4(b0, b1, b2, b3,
                      stB + (uint32_t)((nt * 4 + ct) * 128 + ((l7 ^ ct) * 16)));
                mma16(acc[0][2 * j],     a[0], b0, b1);
                mma16(acc[0][2 * j + 1], a[0], b2, b3);
                mma16(acc[1][2 * j],     a[1], b0, b1);
                mma16(acc[1][2 * j + 1], a[1], b2, b3);
            }
        }
    }

    #pragma unroll
    for (int tm = 0; tm < 2; tm++) {
        int rr = wm * 32 + tm * 16 + (lane >> 2);
        #pragma unroll
        for (int tn = 0; tn < 8; tn++) {
            int cc = bn + wn * 64 + tn * 8 + 2 * (lane & 3);
            float bv0 = 0.0f, bv1 = 0.0f;
            if (isInp) {
                bv0 = bih[cc] + bhh[cc];
                bv1 = bih[cc + 1] + bhh[cc + 1];
            }
            *(float2*)&Cb[(size_t)rr * Gd + cc] =
                make_float2(acc[tm][tn][0] + bv0, acc[tm][tn][1] + bv1);
            *(float2*)&Cb[(size_t)(rr + 8) * Gd + cc] =
                make_float2(acc[tm][tn][2] + bv0, acc[tm][tn][3] + bv1);
        }
    }
}

// ============================================================================
// Phase 2: persistent LSTM, 128 CTAs (R10 body), DATAFLOW sync:
// chunk c (128 h-cols) produced by CTAs 16c..16c+15 -> g_chunk_cnt[c]++ after
// h publish; consumer (tid0 only, no sleep) waits cnt[ks] >= 16t before
// staging chunk ks, piggybacked on existing syncthreads. 4-deep h ring with
// read_done WAR counters. No global per-step barrier.
// ============================================================================
constexpr int NTHR = 256;
constexpr int WS_B = 32 * 1024 * 2;             // 64 KB W tiles
constexpr int SLOT2_B = 128 * 128 * 2;          // 32 KB per 128-col slot
constexpr int SMEM2 = WS_B + 4 * SLOT2_B;       // 192 KB

__global__ void __launch_bounds__(NTHR, 1) lstm_seq_kernel(
    const float* __restrict__ h0, const float* __restrict__ c0in,
    const float* __restrict__ Whh, float* __restrict__ out, int out_size)
{
    extern __shared__ char sm2[];
    const uint32_t sW = s2u(sm2);
    const uint32_t sSt = sW + WS_B;

    const int tid = threadIdx.x, lane = tid & 31, warp = tid >> 5;
    const int cta = blockIdx.x;
    const int ub  = cta * 8;
    const int u0  = ub + 2 * (lane & 3);
    const int b0  = warp * 16 + (lane >> 2);
    const int stag = cta & 7;
    const int mychunk = cta >> 4;            // 128-col chunk this CTA feeds

    // --- W_hh slice -> smem fp16, tile-native layout
    for (int i = tid; i < 32 * 128; i += NTHR) {
        int lr = i >> 7;
        int c  = i & 127;
        int gate = lr >> 3, unit = lr & 7;
        const float* src = Whh + (size_t)(gate * Hd + ub + unit) * Hd + c * 8;
        float4 v0 = *(const float4*)src;
        float4 v1 = *(const float4*)(src + 4);
        uint4 o;
        o.x = h2u(__floats2half2_rn(v0.x, v0.y));
        o.y = h2u(__floats2half2_rn(v0.z, v0.w));
        o.z = h2u(__floats2half2_rn(v1.x, v1.y));
        o.w = h2u(__floats2half2_rn(v1.z, v1.w));
        uint32_t off = (uint32_t)((gate * 128 + c) * 128 + ((unit ^ (c & 7)) * 16));
        *(uint4*)(sm2 + off) = o;
    }

    // t-invariant gate term (bias already folded in by phase 1)
    float2 gxi[4][2];
    #pragma unroll
    for (int q = 0; q < 4; q++)
        #pragma unroll
        for (int bs = 0; bs < 2; bs++) {
            int b = b0 + bs * 8;
            gxi[q][bs] = *(const float2*)&g_gx_inp[(size_t)b * Gd + q * Hd + u0];
        }

    float creg[2][2];
    #pragma unroll
    for (int bs = 0; bs < 2; bs++) {
        int b = b0 + bs * 8;
        creg[bs][0] = c0in[(size_t)b * Hd + u0];
        creg[bs][1] = c0in[(size_t)b * Hd + u0 + 1];
    }

    // initial h (fp16) -> ring slot 0 (each CTA writes one batch row)
    for (int i = tid; i < Hd / 2; i += NTHR) {
        float2 v = *(const float2*)&h0[(size_t)cta * Hd + 2 * i];
        *(__half2*)&g_hring[0][cta * Hd + 2 * i] = __floats2half2_rn(v.x, v.y);
    }
    // one-time full barrier: ring slot 0 + counters visible everywhere
    __syncthreads();
    if (tid == 0) {
        __threadfence();
        unsigned old = atomicAdd(&g_bar_count, 1u);
        if ((old + 1u) % gridDim.x == 0u) { __threadfence(); redrel(&g_bar_gen, 1u); }
        while (ldacq(&g_bar_gen) < 1u) { }
        __threadfence();
    }
    __syncthreads();

    // coalesced staging geometry (R10)
    const int srow_half = lane >> 4;
    const int sc = lane & 15;
    const int shalf = sc >> 3, scc = sc & 7;
    const int g = lane >> 3, l7 = lane & 7;

    for (int t = 0; t < Lt; t++) {
        const __half* cur = g_hring[t & 3];
        __half* nxt = g_hring[(t + 1) & 3];
        const unsigned need = 16u * (unsigned)t;

        float2 gxa[4][2];
        #pragma unroll
        for (int q = 0; q < 4; q++)
            #pragma unroll
            for (int bs = 0; bs < 2; bs++) {
                int b = b0 + bs * 8;
                gxa[q][bs] = *(const float2*)
                    &g_gx_act[((size_t)t * Bt + b) * Gd + q * Hd + u0];
            }

        float acc[4][4];
        #pragma unroll
        for (int q = 0; q < 4; q++)
            #pragma unroll
            for (int k = 0; k < 4; k++) acc[q][k] = 0.0f;

        auto stage = [&](int i) {
            if (i < 8) {
                int ks = (i + stag) & 7;
                uint32_t st = sSt + (uint32_t)(i & 3) * SLOT2_B;
                #pragma unroll
                for (int jj = 0; jj < 8; jj++) {
                    int r = (warp * 8 + jj) * 2 + srow_half;
                    uint32_t off = (uint32_t)(shalf * 16384
                                 + ((r >> 3) * 8 + scc) * 128
                                 + (((r & 7) ^ scc) * 16));
                    cpa16(st + off, cur + (size_t)r * Hd + ks * 128 + sc * 8);
                }
            }
            cpcommit();
        };

        // pre-loop: chunks for stage(0..2) must be ready (tid0 polls, no sleep)
        if (t > 0 && tid == 0) {
            #pragma unroll
            for (int j = 0; j < 3; j++)
                while (ldacq(&g_chunk_cnt[(j + stag) & 7]) < need) { }
        }
        __syncthreads();
        stage(0); stage(1); stage(2);

        for (int i = 0; i < 8; i++) {
            // poll readiness of chunk for stage(i+3) BEFORE the shared sync
            if (t > 0 && i + 3 < 8 && tid == 0) {
                while (ldacq(&g_chunk_cnt[(i + 3 + stag) & 7]) < need) { }
            }
            cpwait<2>(); __syncthreads();
            stage(i + 3);
            const int ks = (i + stag) & 7;
            #pragma unroll
            for (int h = 0; h < 2; h++) {
                const uint32_t st = sSt + (uint32_t)(i & 3) * SLOT2_B
                                  + (uint32_t)h * 16384;
                const int kbg = 2 * ks + h;

                #pragma unroll
                for (int kc = 0; kc < 4; kc++) {
                    uint32_t a[4];
                    {
                        int rt = warp * 2 + (g & 1);
                        int ct = kc * 2 + (g >> 1);
                        ldsm4(a[0], a[1], a[2], a[3],
                              st + (uint32_t)((rt * 8 + ct) * 128 + ((l7 ^ ct) * 16)));
                    }
                    #pragma unroll
                    for (int p = 0; p < 2; p++) {
                        int gate = 2 * p + (g >> 1);
                        int ctg = kbg * 8 + kc * 2 + (g & 1);
                        uint32_t b0r, b1r, b2r, b3r;
                        ldsm4(b0r, b1r, b2r, b3r,
                              sW + (uint32_t)((gate * 128 + ctg) * 128
                                   + ((l7 ^ (ctg & 7)) * 16)));
                        mma16(acc[2 * p],     a, b0r, b1r);
                        mma16(acc[2 * p + 1], a, b2r, b3r);
                    }
                }
            }
        }

        // all reads of ring slot t&3 complete
        cpwait<0>(); __syncthreads();
        if (tid == 0) redrel(&g_read_done[t & 3], 1u);

        // WAR guard: slot (t+1)&3 fully read by all CTAs at its previous use
        if (t + 1 < Lt && t >= 3) {
            if (tid == 0) {
                unsigned wneed = 128u * ((unsigned)(t + 1) >> 2);
                while (ldacq(&g_read_done[(t + 1) & 3]) < wneed) { }
            }
            __syncthreads();
        }

        // cell update -> registers
        float hv[2][2], cv[2][2];
        #pragma unroll
        for (int bs = 0; bs < 2; bs++)
            #pragma unroll
            for (int us = 0; us < 2; us++) {
                int ci = bs * 2 + us;
                float gi = acc[0][ci] + (us ? gxa[0][bs].y : gxa[0][bs].x)
                                      + (us ? gxi[0][bs].y : gxi[0][bs].x);
                float gf = acc[1][ci] + (us ? gxa[1][bs].y : gxa[1][bs].x)
                                      + (us ? gxi[1][bs].y : gxi[1][bs].x);
                float gg = acc[2][ci] + (us ? gxa[2][bs].y : gxa[2][bs].x)
                                      + (us ? gxi[2][bs].y : gxi[2][bs].x);
                float go = acc[3][ci] + (us ? gxa[3][bs].y : gxa[3][bs].x)
                                      + (us ? gxi[3][bs].y : gxi[3][bs].x);
                float cn = sigm(gf) * creg[bs][us] + sigm(gi) * tanhf(gg);
                float hn = sigm(go) * tanhf(cn);
                creg[bs][us] = cn;
                hv[bs][us] = hn; cv[bs][us] = cn;
            }

        if (t + 1 < Lt) {
            // publish h FIRST (2KB, L2-resident -> cheap fence), then signal
            #pragma unroll
            for (int bs = 0; bs < 2; bs++) {
                int b = b0 + bs * 8;
                *(__half2*)&nxt[b * Hd + u0] =
                    __floats2half2_rn(hv[bs][0], hv[bs][1]);
            }
            __syncthreads();
            if (tid == 0) {
                __threadfence();
                redrel(&g_chunk_cnt[mychunk], 1u);
            }
            // out stores ride after the publish
            #pragma unroll
            for (int bs = 0; bs < 2; bs++) {
                int b = b0 + bs * 8;
                size_t ob = (size_t)t * Bt * Hd + (size_t)b * Hd + u0;
                *(float2*)&out[ob] = make_float2(hv[bs][0], hv[bs][1]);
            }
        } else {
            #pragma unroll
            for (int bs = 0; bs < 2; bs++) {
                int b = b0 + bs * 8;
                size_t ob = (size_t)t * Bt * Hd + (size_t)b * Hd + u0;
                *(float2*)&out[ob] = make_float2(hv[bs][0], hv[bs][1]);
                size_t HS = (size_t)Lt * Bt * Hd;
                if ((size_t)out_size >= HS + 2 * (size_t)Bt * Hd) {
                    *(float2*)&out[HS + (size_t)b * Hd + u0] =
                        make_float2(hv[bs][0], hv[bs][1]);
                    *(float2*)&out[HS + (size_t)Bt * Hd + (size_t)b * Hd + u0] =
                        make_float2(cv[bs][0], cv[bs][1]);
                }
            }
        }
    }
}

extern "C" void kernel_launch(void* const* d_in, const int* in_sizes, int n_in,
                              void* d_out, int out_size) {
    (void)in_sizes; (void)n_in;
    const float* act = (const float*)d_in[0];
    const float* inp = (const float*)d_in[1];
    const float* h0  = (const float*)d_in[2];
    const float* c0  = (const float*)d_in[3];
    const float* Wih = (const float*)d_in[4];
    const float* Whh = (const float*)d_in[5];
    const float* bih = (const float*)d_in[6];
    const float* bhh = (const float*)d_in[7];
    float* out = (float*)d_out;

    cudaFuncSetAttribute(gemm_x_h,
                         cudaFuncAttributeMaxDynamicSharedMemorySize, P1_SMEM);
    cudaFuncSetAttribute(lstm_seq_kernel,
                         cudaFuncAttributeMaxDynamicSharedMemorySize, SMEM2);

    prep_kernel<<<1024, 256>>>(act, inp, Wih);
    gemm_x_h<<<dim3(32, 129), 256, P1_SMEM>>>(bih, bhh);
    lstm_seq_kernel<<<128, NTHR, SMEM2>>>(h0, c0, Whh, out, out_size);
}

// round 14
// speedup vs baseline: 2.1338x; 1.8230x over previous
#include <cuda_runtime.h>
#include <cuda_fp16.h>
#include <cstdint>

// Problem dims
constexpr int Lt = 128;
constexpr int Bt = 128;
constexpr int Hd = 1024;
constexpr int Gd = 4 * Hd;       // 4096
constexpr int KA = 512;          // K of both phase-1 sub-GEMMs

// Static scratch
__device__ float g_gx_act[(size_t)Lt * Bt * Gd];     // act-side gate projections
__device__ float g_gx_inp[(size_t)Bt * Gd];          // input-side + biases
__device__ __align__(16) __half g_act_h[(size_t)Lt * Bt * KA];
__device__ __align__(16) __half g_inp_h[(size_t)Bt * KA];
__device__ __align__(16) __half g_wih_h[(size_t)Gd * 1024];
__device__ __align__(16) __half g_hbuf_h[2][Bt * Hd];
__device__ unsigned g_bar_count;
__device__ unsigned g_bar_gen;

// ---------------------------------------------------------------- helpers
__device__ __forceinline__ uint32_t h2u(__half2 v) {
    __half2_raw r = *(__half2_raw*)&v;
    return (uint32_t)r.x | ((uint32_t)r.y << 16);
}
__device__ __forceinline__ void mma16(float* c, const uint32_t* a,
                                      uint32_t b0, uint32_t b1) {
    asm volatile(
        "mma.sync.aligned.m16n8k16.row.col.f32.f16.f16.f32 "
        "{%0,%1,%2,%3},{%4,%5,%6,%7},{%8,%9},{%0,%1,%2,%3};"
        : "+f"(c[0]), "+f"(c[1]), "+f"(c[2]), "+f"(c[3])
        : "r"(a[0]), "r"(a[1]), "r"(a[2]), "r"(a[3]), "r"(b0), "r"(b1));
}
__device__ __forceinline__ void ldsm4(uint32_t& d0, uint32_t& d1,
                                      uint32_t& d2, uint32_t& d3, uint32_t a) {
    asm volatile("ldmatrix.sync.aligned.m8n8.x4.shared.b16 {%0,%1,%2,%3}, [%4];"
                 : "=r"(d0), "=r"(d1), "=r"(d2), "=r"(d3) : "r"(a));
}
__device__ __forceinline__ void cpa16(uint32_t d, const void* s) {
    asm volatile("cp.async.cg.shared.global [%0], [%1], 16;" :: "r"(d), "l"(s));
}
__device__ __forceinline__ void cpcommit() { asm volatile("cp.async.commit_group;"); }
template<int N> __device__ __forceinline__ void cpwait() {
    asm volatile("cp.async.wait_group %0;" :: "n"(N));
}
__device__ __forceinline__ uint32_t s2u(const void* p) {
    return (uint32_t)__cvta_generic_to_shared(p);
}
__device__ __forceinline__ float sigm(float x) { return 1.0f / (1.0f + expf(-x)); }
__device__ __forceinline__ unsigned ldacq(const unsigned* p) {
    unsigned v;
    asm volatile("ld.acquire.gpu.global.u32 %0, [%1];" : "=r"(v) : "l"(p) : "memory");
    return v;
}
__device__ __forceinline__ void redrel(unsigned* p, unsigned v) {
    asm volatile("red.release.gpu.global.add.u32 [%0], %1;" :: "l"(p), "r"(v) : "memory");
}

// ============================================================================
// Prep: fp16-convert act / inp / W_ih; reset sync counters.
// ============================================================================
__global__ void prep_kernel(const float* __restrict__ act,
                            const float* __restrict__ inp,
                            const float* __restrict__ Wih) {
    if (blockIdx.x == 0 && threadIdx.x == 0) { g_bar_count = 0; g_bar_gen = 0; }
    const size_t NW = (size_t)Gd * 1024 / 8;      // 8-elem groups
    const size_t NA = (size_t)Lt * Bt * KA / 8;
    const size_t NI = (size_t)Bt * KA / 8;
    const size_t total = NW + NA + NI;
    for (size_t i = (size_t)blockIdx.x * blockDim.x + threadIdx.x; i < total;
         i += (size_t)gridDim.x * blockDim.x) {
        const float4* s; uint4* d;
        if (i < NW)           { s = (const float4*)Wih + 2 * i;            d = (uint4*)g_wih_h + i; }
        else if (i < NW + NA) { s = (const float4*)act + 2 * (i - NW);     d = (uint4*)g_act_h + (i - NW); }
        else                  { s = (const float4*)inp + 2 * (i - NW - NA); d = (uint4*)g_inp_h + (i - NW - NA); }
        float4 v0 = s[0], v1 = s[1];
        uint4 o;
        o.x = h2u(__floats2half2_rn(v0.x, v0.y));
        o.y = h2u(__floats2half2_rn(v0.z, v0.w));
        o.z = h2u(__floats2half2_rn(v1.x, v1.y));
        o.w = h2u(__floats2half2_rn(v1.z, v1.w));
        *d = o;
    }
}

// ============================================================================
// Phase 1: fp16 m16n8k16 GEMM (R10 coalesced staging + bias fold).
// ============================================================================
constexpr int P1_STG = 4;
constexpr int P1_STAGE_B = 2 * 128 * 32 * 2;   // A 8KB + B 8KB = 16 KB
constexpr int P1_SMEM = P1_STG * P1_STAGE_B;   // 64 KB

__global__ void __launch_bounds__(256, 2) gemm_x_h(const float* __restrict__ bih,
                                                   const float* __restrict__ bhh) {
    extern __shared__ char sm1[];
    const uint32_t sBase = s2u(sm1);

    const int tid = threadIdx.x, lane = tid & 31, warp = tid >> 5;
    const int wm = warp & 3, wn = warp >> 2;
    const bool isInp = (blockIdx.y == 128);
    const int bm = isInp ? 0 : blockIdx.y * 128;
    const int bn = blockIdx.x * 128;
    const __half* Ab = isInp ? g_inp_h : g_act_h + (size_t)bm * KA;
    const __half* Bb = g_wih_h + (size_t)bn * 1024 + (isInp ? 0 : 512);
    float* Cb = isInp ? g_gx_inp : g_gx_act + (size_t)bm * Gd;

    const int c4 = lane & 3;
    const int r8 = lane >> 2;

    auto loadblk = [&](int kb) {
        if (kb < 16) {
            uint32_t st = sBase + (uint32_t)(kb & 3) * P1_STAGE_B;
            #pragma unroll
            for (int j = 0; j < 2; j++) {
                int r = (warp * 2 + j) * 8 + r8;
                uint32_t off = (uint32_t)(((r >> 3) * 4 + c4) * 128
                             + (((r & 7) ^ c4) * 16));
                cpa16(st + off, Ab + (size_t)r * KA + kb * 32 + c4 * 8);
                cpa16(st + 8192 + off, Bb + (size_t)r * 1024 + kb * 32 + c4 * 8);
            }
        }
        cpcommit();
    };

    loadblk(0); loadblk(1); loadblk(2);

    float acc[2][8][4];
    #pragma unroll
    for (int i = 0; i < 2; i++)
        #pragma unroll
        for (int j = 0; j < 8; j++)
            #pragma unroll
            for (int k = 0; k < 4; k++) acc[i][j][k] = 0.0f;

    const int g = lane >> 3;
    const int l7 = lane & 7;

    for (int kb = 0; kb < 16; kb++) {
        cpwait<2>(); __syncthreads();
        loadblk(kb + 3);
        const uint32_t stA = sBase + (uint32_t)(kb & 3) * P1_STAGE_B;
        const uint32_t stB = stA + 8192;

        #pragma unroll
        for (int kc = 0; kc < 2; kc++) {
            uint32_t a[2][4];
            #pragma unroll
            for (int tm = 0; tm < 2; tm++) {
                int rt = wm * 4 + tm * 2 + (g & 1);
                int ct = kc * 2 + (g >> 1);
                ldsm4(a[tm][0], a[tm][1], a[tm][2], a[tm][3],
                      stA + (uint32_t)((rt * 4 + ct) * 128 + ((l7 ^ ct) * 16)));
            }
            #pragma unroll
            for (int j = 0; j < 4; j++) {
                int nt = wn * 8 + 2 * j + (g >> 1);
                int ct = kc * 2 + (g & 1);
                uint32_t b0, b1, b2, b3;
                ldsm4(b0, b1, b2, b3,
                      stB + (uint32_t)((nt * 4 + ct) * 128 + ((l7 ^ ct) * 16)));
                mma16(acc[0][2 * j],     a[0], b0, b1);
                mma16(acc[0][2 * j + 1], a[0], b2, b3);
                mma16(acc[1][2 * j],     a[1], b0, b1);
                mma16(acc[1][2 * j + 1], a[1], b2, b3);
            }
        }
    }

    #pragma unroll
    for (int tm = 0; tm < 2; tm++) {
        int rr = wm * 32 + tm * 16 + (lane >> 2);
        #pragma unroll
        for (int tn = 0; tn < 8; tn++) {
            int cc = bn + wn * 64 + tn * 8 + 2 * (lane & 3);
            float bv0 = 0.0f, bv1 = 0.0f;
            if (isInp) {
                bv0 = bih[cc] + bhh[cc];
                bv1 = bih[cc + 1] + bhh[cc + 1];
            }
            *(float2*)&Cb[(size_t)rr * Gd + cc] =
                make_float2(acc[tm][tn][0] + bv0, acc[tm][tn][1] + bv1);
            *(float2*)&Cb[(size_t)(rr + 8) * Gd + cc] =
                make_float2(acc[tm][tn][2] + bv0, acc[tm][tn][3] + bv1);
        }
    }
}

// ============================================================================
// Phase 2: persistent LSTM, 128 CTAs, WARP-PRIVATE step pipelines.
// Warp mw stages ONLY its own 16 batch rows (4KB/slot, private 4-deep ring,
// per-thread cp.async groups) -> ZERO syncthreads in the GEMM loop; warps
// run decoupled. One syncthreads + barrier per step; out stores ride the
// barrier-wait window. Accumulation order identical to R10.
// ============================================================================
constexpr int NTHR = 256;
constexpr int WS_B = 32 * 1024 * 2;             // 64 KB W tiles
constexpr int WSLOT_B = 16 * 256;               // 4 KB per warp per slot
constexpr int SMEM2 = WS_B + 8 * 4 * WSLOT_B;   // 64 + 128 = 192 KB

__global__ void __launch_bounds__(NTHR, 1) lstm_seq_kernel(
    const float* __restrict__ h0, const float* __restrict__ c0in,
    const float* __restrict__ Whh, float* __restrict__ out, int out_size)
{
    extern __shared__ char sm2[];
    const uint32_t sW = s2u(sm2);
    const uint32_t sSt = sW + WS_B;

    const int tid = threadIdx.x, lane = tid & 31, warp = tid >> 5;
    const int cta = blockIdx.x;
    const int ub  = cta * 8;
    const int u0  = ub + 2 * (lane & 3);
    const int b0  = warp * 16 + (lane >> 2);
    const int stag = cta & 7;

    // --- W_hh slice -> smem fp16, tile-native layout (as R10)
    for (int i = tid; i < 32 * 128; i += NTHR) {
        int lr = i >> 7;
        int c  = i & 127;
        int gate = lr >> 3, unit = lr & 7;
        const float* src = Whh + (size_t)(gate * Hd + ub + unit) * Hd + c * 8;
        float4 v0 = *(const float4*)src;
        float4 v1 = *(const float4*)(src + 4);
        uint4 o;
        o.x = h2u(__floats2half2_rn(v0.x, v0.y));
        o.y = h2u(__floats2half2_rn(v0.z, v0.w));
        o.z = h2u(__floats2half2_rn(v1.x, v1.y));
        o.w = h2u(__floats2half2_rn(v1.z, v1.w));
        uint32_t off = (uint32_t)((gate * 128 + c) * 128 + ((unit ^ (c & 7)) * 16));
        *(uint4*)(sm2 + off) = o;
    }

    // t-invariant gate term (bias folded in by phase 1)
    float2 gxi[4][2];
    #pragma unroll
    for (int q = 0; q < 4; q++)
        #pragma unroll
        for (int bs = 0; bs < 2; bs++) {
            int b = b0 + bs * 8;
            gxi[q][bs] = *(const float2*)&g_gx_inp[(size_t)b * Gd + q * Hd + u0];
        }

    float creg[2][2];
    #pragma unroll
    for (int bs = 0; bs < 2; bs++) {
        int b = b0 + bs * 8;
        creg[bs][0] = c0in[(size_t)b * Hd + u0];
        creg[bs][1] = c0in[(size_t)b * Hd + u0 + 1];
    }

    // initial h (fp16) -> buffer 0
    for (int i = tid; i < Hd / 2; i += NTHR) {
        float2 v = *(const float2*)&h0[(size_t)cta * Hd + 2 * i];
        *(__half2*)&g_hbuf_h[0][cta * Hd + 2 * i] = __floats2half2_rn(v.x, v.y);
    }
    // one-time full barrier
    __syncthreads();
    if (tid == 0) {
        __threadfence();
        unsigned old = atomicAdd(&g_bar_count, 1u);
        if ((old + 1u) % gridDim.x == 0u) { __threadfence(); redrel(&g_bar_gen, 1u); }
        while (ldacq(&g_bar_gen) < 1u) { }
        __threadfence();
    }
    __syncthreads();

    // per-warp staging geometry: slot = 16 rows x 128 cols (4 KB).
    // lane -> (row_half = lane>>4, chunk sc = lane&15); store chunk c of row r
    // at r*256 + ((c ^ (r&7)) * 16)  (conflict-free stores & ldsm reads).
    const uint32_t wbase = sSt + (uint32_t)warp * (4 * WSLOT_B);
    const int srh = lane >> 4;              // row parity within row pair
    const int sc = lane & 15;               // 16B chunk 0..15
    const int g = lane >> 3, l7 = lane & 7;
    const int aro = ((g & 1) << 3) + l7;    // local A row for ldsm

    for (int t = 0; t < Lt; t++) {
        const __half* cur = g_hbuf_h[t & 1];
        __half* nxt = g_hbuf_h[(t + 1) & 1];

        float2 gxa[4][2];
        #pragma unroll
        for (int q = 0; q < 4; q++)
            #pragma unroll
            for (int bs = 0; bs < 2; bs++) {
                int b = b0 + bs * 8;
                gxa[q][bs] = *(const float2*)
                    &g_gx_act[((size_t)t * Bt + b) * Gd + q * Hd + u0];
            }

        float acc[4][4];
        #pragma unroll
        for (int q = 0; q < 4; q++)
            #pragma unroll
            for (int k = 0; k < 4; k++) acc[q][k] = 0.0f;

        // warp-private stage of slot s (k-slot ks=(s+stag)&7): 8 cpa16/thread
        auto stage = [&](int s) {
            if (s < 8) {
                int ks = (s + stag) & 7;
                uint32_t st = wbase + (uint32_t)(s & 3) * WSLOT_B;
                #pragma unroll
                for (int jj = 0; jj < 8; jj++) {
                    int r = jj * 2 + srh;           // local row 0..15
                    uint32_t off = (uint32_t)(r * 256 + ((sc ^ (r & 7)) * 16));
                    cpa16(st + off,
                          cur + (size_t)(warp * 16 + r) * Hd + ks * 128 + sc * 8);
                }
            }
            cpcommit();
        };

        stage(0); stage(1); stage(2);

        for (int s = 0; s < 8; s++) {
            cpwait<2>();                    // own groups only — no syncthreads!
            stage(s + 3);
            const int ks = (s + stag) & 7;
            const uint32_t st = wbase + (uint32_t)(s & 3) * WSLOT_B;

            #pragma unroll
            for (int kk = 0; kk < 8; kk++) {        // 8 k16-steps per slot
                uint32_t a[4];
                {
                    int ct = kk * 2 + (g >> 1);     // 16B chunk 0..15
                    ldsm4(a[0], a[1], a[2], a[3],
                          st + (uint32_t)(aro * 256 + ((ct ^ (aro & 7)) * 16)));
                }
                #pragma unroll
                for (int p = 0; p < 2; p++) {
                    int gate = 2 * p + (g >> 1);
                    int gck = ks * 16 + kk * 2 + (g & 1);   // global 16B chunk
                    uint32_t b0r, b1r, b2r, b3r;
                    ldsm4(b0r, b1r, b2r, b3r,
                          sW + (uint32_t)((gate * 128 + gck) * 128
                               + ((l7 ^ (gck & 7)) * 16)));
                    mma16(acc[2 * p],     a, b0r, b1r);
                    mma16(acc[2 * p + 1], a, b2r, b3r);
                }
            }
        }
        cpwait<0>();

        // cell update -> registers (per-warp local)
        float hv[2][2], cv[2][2];
        #pragma unroll
        for (int bs = 0; bs < 2; bs++)
            #pragma unroll
            for (int us = 0; us < 2; us++) {
                int ci = bs * 2 + us;
                float gi = acc[0][ci] + (us ? gxa[0][bs].y : gxa[0][bs].x)
                                      + (us ? gxi[0][bs].y : gxi[0][bs].x);
                float gf = acc[1][ci] + (us ? gxa[1][bs].y : gxa[1][bs].x)
                                      + (us ? gxi[1][bs].y : gxi[1][bs].x);
                float gg = acc[2][ci] + (us ? gxa[2][bs].y : gxa[2][bs].x)
                                      + (us ? gxi[2][bs].y : gxi[2][bs].x);
                float go = acc[3][ci] + (us ? gxa[3][bs].y : gxa[3][bs].x)
                                      + (us ? gxi[3][bs].y : gxi[3][bs].x);
                float cn = sigm(gf) * creg[bs][us] + sigm(gi) * tanhf(gg);
                float hn = sigm(go) * tanhf(cn);
                creg[bs][us] = cn;
                hv[bs][us] = hn; cv[bs][us] = cn;
            }

        if (t + 1 < Lt) {
            // publish h first (2KB, L2), then one rendezvous per step
            #pragma unroll
            for (int bs = 0; bs < 2; bs++) {
                int b = b0 + bs * 8;
                *(__half2*)&nxt[b * Hd + u0] =
                    __floats2half2_rn(hv[bs][0], hv[bs][1]);
            }
            __syncthreads();
            if (tid == 0) {
                __threadfence();
                unsigned old = atomicAdd(&g_bar_count, 1u);
                if ((old + 1u) % gridDim.x == 0u) {
                    __threadfence();
                    redrel(&g_bar_gen, 1u);
                }
            }
            // out stores ride inside the wait window
            #pragma unroll
            for (int bs = 0; bs < 2; bs++) {
                int b = b0 + bs * 8;
                size_t ob = (size_t)t * Bt * Hd + (size_t)b * Hd + u0;
                *(float2*)&out[ob] = make_float2(hv[bs][0], hv[bs][1]);
            }
            if (tid == 0) {
                while (ldacq(&g_bar_gen) < (unsigned)(t + 2)) { }
            }
            __syncthreads();
        } else {
            #pragma unroll
            for (int bs = 0; bs < 2; bs++) {
                int b = b0 + bs * 8;
                size_t ob = (size_t)t * Bt * Hd + (size_t)b * Hd + u0;
                *(float2*)&out[ob] = make_float2(hv[bs][0], hv[bs][1]);
                size_t HS = (size_t)Lt * Bt * Hd;
                if ((size_t)out_size >= HS + 2 * (size_t)Bt * Hd) {
                    *(float2*)&out[HS + (size_t)b * Hd + u0] =
                        make_float2(hv[bs][0], hv[bs][1]);
                    *(float2*)&out[HS + (size_t)Bt * Hd + (size_t)b * Hd + u0] =
                        make_float2(cv[bs][0], cv[bs][1]);
                }
            }
        }
    }
}

extern "C" void kernel_launch(void* const* d_in, const int* in_sizes, int n_in,
                              void* d_out, int out_size) {
    (void)in_sizes; (void)n_in;
    const float* act = (const float*)d_in[0];
    const float* inp = (const float*)d_in[1];
    const float* h0  = (const float*)d_in[2];
    const float* c0  = (const float*)d_in[3];
    const float* Wih = (const float*)d_in[4];
    const float* Whh = (const float*)d_in[5];
    const float* bih = (const float*)d_in[6];
    const float* bhh = (const float*)d_in[7];
    float* out = (float*)d_out;

    cudaFuncSetAttribute(gemm_x_h,
                         cudaFuncAttributeMaxDynamicSharedMemorySize, P1_SMEM);
    cudaFuncSetAttribute(lstm_seq_kernel,
                         cudaFuncAttributeMaxDynamicSharedMemorySize, SMEM2);

    prep_kernel<<<1024, 256>>>(act, inp, Wih);
    gemm_x_h<<<dim3(32, 129), 256, P1_SMEM>>>(bih, bhh);
    lstm_seq_kernel<<<128, NTHR, SMEM2>>>(h0, c0, Whh, out, out_size);
}